// round 16
// baseline (speedup 1.0000x reference)
#include <cuda_runtime.h>
#include <cuda_fp16.h>
#include <cuda_bf16.h>
#include <cstdint>

typedef unsigned long long u64;
typedef unsigned int u32;

// ---------------- scratch ----------------
__device__ float g_pre_ox[512 * 64];
__device__ float g_pre_tp[512 * 64];
__device__ float g_stats[512 * 18];
__device__ float g_pts[512 * 1000 * 2];
__device__ float g_targets[512 * 1000 * 2];
__device__ float g_off_part[512 * 4];
__device__ float g_cls[512];
__device__ float g_endsum[512];
__device__ uint4 g_w4[16 * 64];
__device__ int   g_bdone[512];
__device__ float* g_outbuf;

// ---------------- packed f32x2 helpers ----------------
__device__ __forceinline__ u64 F2(float a, float b) {
    u64 r; asm("mov.b64 %0,{%1,%2};" : "=l"(r) : "f"(a), "f"(b)); return r;
}
__device__ __forceinline__ void UNPK(u64 v, float& a, float& b) {
    asm("mov.b64 {%0,%1},%2;" : "=f"(a), "=f"(b) : "l"(v));
}
__device__ __forceinline__ u64 FMA2(u64 a, u64 b, u64 c) {
    u64 d; asm("fma.rn.f32x2 %0,%1,%2,%3;" : "=l"(d) : "l"(a), "l"(b), "l"(c)); return d;
}
__device__ __forceinline__ u64 ADD2(u64 a, u64 b) {
    u64 d; asm("add.rn.f32x2 %0,%1,%2;" : "=l"(d) : "l"(a), "l"(b)); return d;
}
__device__ __forceinline__ u64 MUL2(u64 a, u64 b) {
    u64 d; asm("mul.rn.f32x2 %0,%1,%2;" : "=l"(d) : "l"(a), "l"(b)); return d;
}
__device__ __forceinline__ u64 LD2(const float* p) {
    return *reinterpret_cast<const u64*>(p);
}
__device__ __forceinline__ u64 C2(float c) { return F2(c, c); }

__device__ __forceinline__ float sl1(float z) {
    float d = fabsf(z);
    return d < 1.0f ? 0.5f * d * d : d - 0.5f;
}

// Packed branchless exact-GELU (A&S 7.1.26 erfc, -0.5 folded into coefficients).
__device__ __forceinline__ u64 fast_gelu2(u64 z2) {
    u64 az = z2 & 0x7fffffff7fffffffull;
    u64 u2 = MUL2(az, C2(0.70710678118654752f));
    u64 dn = FMA2(u2, C2(0.3275911f), C2(1.0f));
    float d0, d1; UNPK(dn, d0, d1);
    float t0, t1;
    asm("rcp.approx.f32 %0, %1;" : "=f"(t0) : "f"(d0));
    asm("rcp.approx.f32 %0, %1;" : "=f"(t1) : "f"(d1));
    u64 t2 = F2(t0, t1);
    u64 gg = MUL2(MUL2(u2, u2), C2(-1.4426950408889634f));
    float g0, g1; UNPK(gg, g0, g1);
    float e0, e1;
    asm("ex2.approx.f32 %0, %1;" : "=f"(e0) : "f"(g0));
    asm("ex2.approx.f32 %0, %1;" : "=f"(e1) : "f"(g1));
    u64 p2 = FMA2(t2, C2(-0.5307027145f), C2(0.7265760135f));
    p2 = FMA2(p2, t2, C2(-0.7107068705f));
    p2 = FMA2(p2, t2, C2(0.142248368f));
    p2 = FMA2(p2, t2, C2(-0.127414796f));
    u64 q2 = MUL2(MUL2(p2, t2), F2(e0, e1));
    float z0, z1; UNPK(z2, z0, z1);
    u64 rl = F2(fmaxf(z0, 0.f), fmaxf(z1, 0.f));
    return FMA2(az, q2, rl);
}

// split f32 pair -> f16x2 hi + f16x2 residual lo
__device__ __forceinline__ void hsplit(u64 xy, u32& h, u32& l) {
    float x, y; UNPK(xy, x, y);
    __half2 hh = __floats2half2_rn(x, y);
    h = *reinterpret_cast<u32*>(&hh);
    float2 bk = __half22float2(hh);
    __half2 hl = __floats2half2_rn(x - bk.x, y - bk.y);
    l = *reinterpret_cast<u32*>(&hl);
}

// m16n8k16 fp16 MMA, f32 accum, D += A*B
__device__ __forceinline__ void mma16f(float* c, const u32* a, u32 b0, u32 b1) {
    asm volatile(
        "mma.sync.aligned.m16n8k16.row.col.f32.f16.f16.f32 "
        "{%0,%1,%2,%3},{%4,%5,%6,%7},{%8,%9},{%0,%1,%2,%3};"
        : "+f"(c[0]), "+f"(c[1]), "+f"(c[2]), "+f"(c[3])
        : "r"(a[0]), "r"(a[1]), "r"(a[2]), "r"(a[3]), "r"(b0), "r"(b1));
}

__device__ __forceinline__ float qsum(float v) {
    v += __shfl_xor_sync(0xffffffffu, v, 1);
    v += __shfl_xor_sync(0xffffffffu, v, 2);
    return v;
}
__device__ __forceinline__ float wsum(float v) {
#pragma unroll
    for (int o = 16; o; o >>= 1) v += __shfl_xor_sync(0xffffffffu, v, o);
    return v;
}

// Closed-form LN (stats precomputed) + packed GELU on two fragment rows.
__device__ __forceinline__ void ln_gelu_closed(u64* hA, u64* hB,
                                               float mA, float rA, float mB, float rB,
                                               const float* gp, const float* bep, int tig) {
    u64 rA2 = C2(rA), rB2 = C2(rB);
    u64 nmrA = C2(-mA * rA), nmrB = C2(-mB * rB);
#pragma unroll
    for (int j = 0; j < 8; j++) {
        int o = 8 * j + 2 * tig;
        u64 g2 = LD2(&gp[o]), be2 = LD2(&bep[o]);
        u64 offA = FMA2(nmrA, g2, be2);
        u64 offB = FMA2(nmrB, g2, be2);
        hA[j] = fast_gelu2(FMA2(hA[j], MUL2(rA2, g2), offA));
        hB[j] = fast_gelu2(FMA2(hB[j], MUL2(rB2, g2), offB));
    }
}

__global__ void set_outbuf_kernel(float* p) { g_outbuf = p; }

// ---------------- K1: FUSED setup (R15 body + counter reset) ----------------
__global__ void __launch_bounds__(1024) setup_kernel(
    const float* __restrict__ osm,
    const float* __restrict__ at, const float* __restrict__ vf,
    const float* __restrict__ ox_w1, const float* __restrict__ ox_b1,
    const float* __restrict__ tp_w1, const float* __restrict__ tp_b1,
    const float* __restrict__ tp_w2) {
    __shared__ u64 s[2048];
    __shared__ float s_vf[64], s_at[64];
    __shared__ float pa[4][64], pt[4][64];
    __shared__ float s_pox[64], s_ptp[64];

    int b = blockIdx.x, t = threadIdx.x;
    int wd = t >> 5, lane = t & 31;

    if (t == 0) g_bdone[b] = 0;

    u64 k0, k1;
    {
        int m0 = 64 * wd + lane, m1 = m0 + 32;
        float x = osm[(b * 2000 + m0) * 4];
        float y = osm[(b * 2000 + m0) * 4 + 1];
        k0 = (m0 < 2000) ? (((u64)__float_as_uint(x * x + y * y) << 32) | (u32)m0) : ~0ull;
        if (m1 < 2000) {
            float x1 = osm[(b * 2000 + m1) * 4];
            float y1 = osm[(b * 2000 + m1) * 4 + 1];
            k1 = ((u64)__float_as_uint(x1 * x1 + y1 * y1) << 32) | (u32)m1;
        } else k1 = ~0ull;
    }

    if (b == 0) {
#pragma unroll
        for (int i = t; i < 2048; i += 1024) {
            int kp = i >> 6, n = i & 63;
            float w0 = tp_w2[(2 * kp) * 64 + n];
            float w1 = tp_w2[(2 * kp + 1) * 64 + n];
            __half2 hh = __floats2half2_rn(w0, w1);
            u32 hi = *reinterpret_cast<u32*>(&hh);
            float2 bk = __half22float2(hh);
            __half2 hl = __floats2half2_rn(w0 - bk.x, w1 - bk.y);
            u32 lo = *reinterpret_cast<u32*>(&hl);
            int kt = kp >> 3, rem = kp & 7;
            int row = kt * 4 + (rem & 3);
            int second = rem >> 2;
            u32* base = reinterpret_cast<u32*>(&g_w4[row * 64 + n]);
            base[second]     = hi;
            base[2 + second] = lo;
        }
    }

    if (t < 64) { s_vf[t] = vf[b * 64 + t]; s_at[t] = at[b * 64 + t]; }
    __syncthreads();
    if (t < 256) {
        int c = t & 63, kq = t >> 6;
        float a = 0.f, tt = 0.f;
#pragma unroll
        for (int k = kq * 16; k < kq * 16 + 16; k++) {
            a  += s_vf[k] * ox_w1[k * 64 + c] + s_at[k] * ox_w1[(64 + k) * 64 + c];
            tt += s_vf[k] * tp_w1[k * 64 + c] + s_at[k] * tp_w1[(64 + k) * 64 + c];
        }
        pa[kq][c] = a; pt[kq][c] = tt;
    }
    __syncthreads();
    if (t < 64) {
        float pox = pa[0][t] + pa[1][t] + pa[2][t] + pa[3][t] + ox_b1[t];
        float ptp = pt[0][t] + pt[1][t] + pt[2][t] + pt[3][t] + tp_b1[t];
        g_pre_ox[b * 64 + t] = pox;
        g_pre_tp[b * 64 + t] = ptp;
        s_pox[t] = pox; s_ptp[t] = ptp;
    }
    __syncthreads();
    if (wd < 2) {
        const float* pre = (wd == 0) ? s_pox : s_ptp;
        const float* w1  = (wd == 0) ? ox_w1 : tp_w1;
        float p0 = pre[2 * lane],           p1 = pre[2 * lane + 1];
        float x0 = w1[128 * 64 + 2 * lane], x1 = w1[128 * 64 + 2 * lane + 1];
        float y0 = w1[129 * 64 + 2 * lane], y1 = w1[129 * 64 + 2 * lane + 1];
        float v[9];
        v[0] = p0 + p1;           v[1] = x0 + x1;           v[2] = y0 + y1;
        v[3] = p0 * p0 + p1 * p1; v[4] = x0 * x0 + x1 * x1; v[5] = y0 * y0 + y1 * y1;
        v[6] = p0 * x0 + p1 * x1; v[7] = p0 * y0 + p1 * y1; v[8] = x0 * y0 + x1 * y1;
#pragma unroll
        for (int k = 0; k < 9; k++) v[k] = wsum(v[k]);
        if (lane == 0) {
#pragma unroll
            for (int k = 0; k < 9; k++)
                g_stats[b * 18 + wd * 9 + k] = v[k] * 0.015625f * (k >= 6 ? 2.0f : 1.0f);
        }
    }

#pragma unroll
    for (int k = 2; k <= 32; k <<= 1) {
#pragma unroll
        for (int j = k >> 1; j > 0; j >>= 1) {
            u64 o0 = __shfl_xor_sync(0xffffffffu, k0, j);
            u64 o1 = __shfl_xor_sync(0xffffffffu, k1, j);
            bool low = (lane & j) == 0;
            bool up0 = (lane & k) == 0;
            bool up1 = ((lane + 32) & k) == 0;
            bool t0 = (low != up0), t1 = (low != up1);
            k0 = t0 ? (k0 > o0 ? k0 : o0) : (k0 < o0 ? k0 : o0);
            k1 = t1 ? (k1 > o1 ? k1 : o1) : (k1 < o1 ? k1 : o1);
        }
    }
    {
        bool up = ((wd & 1) == 0);
        u64 lo = k0 < k1 ? k0 : k1, hi = k0 < k1 ? k1 : k0;
        k0 = up ? lo : hi; k1 = up ? hi : lo;
#pragma unroll
        for (int j = 16; j > 0; j >>= 1) {
            u64 o0 = __shfl_xor_sync(0xffffffffu, k0, j);
            u64 o1 = __shfl_xor_sync(0xffffffffu, k1, j);
            bool low = (lane & j) == 0;
            bool tk = (low != up);
            k0 = tk ? (k0 > o0 ? k0 : o0) : (k0 < o0 ? k0 : o0);
            k1 = tk ? (k1 > o1 ? k1 : o1) : (k1 < o1 ? k1 : o1);
        }
    }
    s[64 * wd + lane] = k0;
    s[64 * wd + 32 + lane] = k1;

#pragma unroll 1
    for (int k = 128; k <= 2048; k <<= 1) {
#pragma unroll 1
        for (int j = k >> 1; j >= 64; j >>= 1) {
            __syncthreads();
            int i0 = ((t & ~(j - 1)) << 1) | (t & (j - 1));
            int i1 = i0 | j;
            bool up = ((i0 & k) == 0);
            u64 A = s[i0], B = s[i1];
            if ((A > B) == up) { s[i0] = B; s[i1] = A; }
        }
        __syncthreads();
        k0 = s[64 * wd + lane];
        k1 = s[64 * wd + 32 + lane];
        bool up = (((wd << 6) & k) == 0);
        {
            u64 lo = k0 < k1 ? k0 : k1, hi = k0 < k1 ? k1 : k0;
            k0 = up ? lo : hi; k1 = up ? hi : lo;
        }
#pragma unroll
        for (int j = 16; j > 0; j >>= 1) {
            u64 o0 = __shfl_xor_sync(0xffffffffu, k0, j);
            u64 o1 = __shfl_xor_sync(0xffffffffu, k1, j);
            bool low = (lane & j) == 0;
            bool tk = (low != up);
            k0 = tk ? (k0 > o0 ? k0 : o0) : (k0 < o0 ? k0 : o0);
            k1 = tk ? (k1 > o1 ? k1 : o1) : (k1 < o1 ? k1 : o1);
        }
        s[64 * wd + lane] = k0;
        s[64 * wd + 32 + lane] = k1;
    }
    __syncthreads();

    if (t < 1000) {
        u32 m = (u32)(s[t] & 0xffffffffull);
        g_pts[(b * 1000 + t) * 2]     = osm[(b * 2000 + m) * 4];
        g_pts[(b * 1000 + t) * 2 + 1] = osm[(b * 2000 + m) * 4 + 1];
    }
}

// ---------------- K2: FUSED per-point MLP + last-block per-batch finalize ----------------
#define W4STR 66
#define MLP_DSMEM 28288

#define T_PRE_OX 0
#define T_OXX    1
#define T_OXY    2
#define T_OXG    3
#define T_OXBE   4
#define T_W2A    5
#define T_W2B    6
#define T_PRE_TP 7
#define T_TPX    8
#define T_TPY    9
#define T_G1     10
#define T_BE1    11

__global__ void __launch_bounds__(256, 3) mlp_kernel(
    const float* __restrict__ ox_w1, const float* __restrict__ ox_g1, const float* __restrict__ ox_be1,
    const float* __restrict__ ox_w2, const float* __restrict__ ox_b2,
    const float* __restrict__ tp_w1, const float* __restrict__ tp_g1, const float* __restrict__ tp_be1,
    const float* __restrict__ tp_w2, const float* __restrict__ tp_b2,
    const float* __restrict__ tp_g2, const float* __restrict__ tp_be2,
    const float* __restrict__ tp_w3, const float* __restrict__ tp_b3,
    const float* __restrict__ end) {
    extern __shared__ __align__(16) char dsm[];
    uint4* w4 = reinterpret_cast<uint4*>(dsm);
    __shared__ __align__(16) float P[12][64];
    __shared__ __align__(16) float s_b2[64], s_g2[64], s_be2[64], s_w3[128];
    __shared__ float s_red[256];
    __shared__ float s_st[18];
    __shared__ float s_w[16];
    __shared__ int   s_wi[8];
    __shared__ float s_bc[8];
    __shared__ int s_bi;
    __shared__ int s_flag;

    int b = blockIdx.y;
    int tid = threadIdx.x;
    int wid = tid >> 5, lane = tid & 31;

    if (tid < 64) {
        P[T_PRE_OX][tid] = g_pre_ox[b * 64 + tid];
        P[T_PRE_TP][tid] = g_pre_tp[b * 64 + tid];
        P[T_OXX][tid] = ox_w1[128 * 64 + tid];
        P[T_OXY][tid] = ox_w1[129 * 64 + tid];
        P[T_TPX][tid] = tp_w1[128 * 64 + tid];
        P[T_TPY][tid] = tp_w1[129 * 64 + tid];
        P[T_OXG][tid] = ox_g1[tid];
        P[T_OXBE][tid] = ox_be1[tid];
        P[T_G1][tid] = tp_g1[tid];
        P[T_BE1][tid] = tp_be1[tid];
        P[T_W2A][tid] = ox_w2[2 * tid];
        P[T_W2B][tid] = ox_w2[2 * tid + 1];
        s_b2[tid] = tp_b2[tid]; s_g2[tid] = tp_g2[tid]; s_be2[tid] = tp_be2[tid];
    }
    if (tid < 128) s_w3[tid] = tp_w3[tid];
    if (tid >= 128 && tid < 146) s_st[tid - 128] = g_stats[b * 18 + tid - 128];
#pragma unroll
    for (int i = tid; i < 1024; i += 256) {
        w4[(i >> 6) * W4STR + (i & 63)] = g_w4[i];
    }
    __syncthreads();

    int gid = lane >> 2, tig = lane & 3;
    float ex = end[2 * b], ey = end[2 * b + 1];
    float b2o0 = ox_b2[0], b2o1 = ox_b2[1];
    float b3_0 = tp_b3[0], b3_1 = tp_b3[1];
    float smAcc = 0.f;

#pragma unroll 1
    for (int mt = 0; mt < 2; mt++) {
        int iA = blockIdx.x * 256 + wid * 32 + mt * 16 + gid;
        int iB = iA + 8;
        float xA = 0.f, yA = 0.f, xB = 0.f, yB = 0.f;
        if (iA < 1000) { float2 v = *reinterpret_cast<const float2*>(&g_pts[(b * 1000 + iA) * 2]); xA = v.x; yA = v.y; }
        if (iB < 1000) { float2 v = *reinterpret_cast<const float2*>(&g_pts[(b * 1000 + iB) * 2]); xB = v.x; yB = v.y; }

        u64 hA[8], hB[8];
        {
            u64 xA2 = F2(xA, xA), yA2 = F2(yA, yA), xB2 = F2(xB, xB), yB2 = F2(yB, yB);
#pragma unroll
            for (int j = 0; j < 8; j++) {
                int o = 8 * j + 2 * tig;
                u64 pre = LD2(&P[T_PRE_OX][o]), wx = LD2(&P[T_OXX][o]), wy = LD2(&P[T_OXY][o]);
                hA[j] = FMA2(yA2, wy, FMA2(xA2, wx, pre));
                hB[j] = FMA2(yB2, wy, FMA2(xB2, wx, pre));
            }
        }
        {
            float mA = fmaf(yA, s_st[2], fmaf(xA, s_st[1], s_st[0]));
            float mB = fmaf(yB, s_st[2], fmaf(xB, s_st[1], s_st[0]));
            float eA = fmaf(yA, fmaf(yA, s_st[5], s_st[7]),
                       fmaf(xA, fmaf(yA, s_st[8], fmaf(xA, s_st[4], s_st[6])), s_st[3]));
            float eB = fmaf(yB, fmaf(yB, s_st[5], s_st[7]),
                       fmaf(xB, fmaf(yB, s_st[8], fmaf(xB, s_st[4], s_st[6])), s_st[3]));
            float rA = rsqrtf(fmaf(-mA, mA, eA) + 1e-5f);
            float rB = rsqrtf(fmaf(-mB, mB, eB) + 1e-5f);
            ln_gelu_closed(hA, hB, mA, rA, mB, rB, &P[T_OXG][0], &P[T_OXBE][0], tig);
        }

        float txA, tyA, txB, tyB;
        {
            u64 axA = F2(0.f, 0.f), ayA = axA, axB = axA, ayB = axA;
#pragma unroll
            for (int j = 0; j < 8; j++) {
                int o = 8 * j + 2 * tig;
                u64 wa = LD2(&P[T_W2A][o]), wb = LD2(&P[T_W2B][o]);
                axA = FMA2(hA[j], wa, axA); ayA = FMA2(hA[j], wb, ayA);
                axB = FMA2(hB[j], wa, axB); ayB = FMA2(hB[j], wb, ayB);
            }
            float p0, p1;
            UNPK(axA, p0, p1); txA = xA + qsum(p0 + p1) + b2o0;
            UNPK(ayA, p0, p1); tyA = yA + qsum(p0 + p1) + b2o1;
            UNPK(axB, p0, p1); txB = xB + qsum(p0 + p1) + b2o0;
            UNPK(ayB, p0, p1); tyB = yB + qsum(p0 + p1) + b2o1;
        }

        {
            u64 xA2 = F2(txA, txA), yA2 = F2(tyA, tyA), xB2 = F2(txB, txB), yB2 = F2(tyB, tyB);
#pragma unroll
            for (int j = 0; j < 8; j++) {
                int o = 8 * j + 2 * tig;
                u64 pre = LD2(&P[T_PRE_TP][o]), wx = LD2(&P[T_TPX][o]), wy = LD2(&P[T_TPY][o]);
                hA[j] = FMA2(yA2, wy, FMA2(xA2, wx, pre));
                hB[j] = FMA2(yB2, wy, FMA2(xB2, wx, pre));
            }
        }
        {
            float mA = fmaf(tyA, s_st[11], fmaf(txA, s_st[10], s_st[9]));
            float mB = fmaf(tyB, s_st[11], fmaf(txB, s_st[10], s_st[9]));
            float eA = fmaf(tyA, fmaf(tyA, s_st[14], s_st[16]),
                       fmaf(txA, fmaf(tyA, s_st[17], fmaf(txA, s_st[13], s_st[15])), s_st[12]));
            float eB = fmaf(tyB, fmaf(tyB, s_st[14], s_st[16]),
                       fmaf(txB, fmaf(tyB, s_st[17], fmaf(txB, s_st[13], s_st[15])), s_st[12]));
            float rA = rsqrtf(fmaf(-mA, mA, eA) + 1e-5f);
            float rB = rsqrtf(fmaf(-mB, mB, eB) + 1e-5f);
            ln_gelu_closed(hA, hB, mA, rA, mB, rB, &P[T_G1][0], &P[T_BE1][0], tig);
        }

        float cst[8][4];
#pragma unroll
        for (int nt = 0; nt < 8; nt++)
#pragma unroll
            for (int qq = 0; qq < 4; qq++) cst[nt][qq] = 0.f;

#pragma unroll
        for (int kt = 0; kt < 4; kt++) {
            u32 ah[4], al[4];
            hsplit(hA[2 * kt],     ah[0], al[0]);
            hsplit(hB[2 * kt],     ah[1], al[1]);
            hsplit(hA[2 * kt + 1], ah[2], al[2]);
            hsplit(hB[2 * kt + 1], ah[3], al[3]);
            const uint4* rp = &w4[(kt * 4 + tig) * W4STR];
#pragma unroll
            for (int nt = 0; nt < 8; nt++) {
                uint4 w = rp[8 * nt + gid];
                mma16f(cst[nt], ah, w.x, w.y);
                mma16f(cst[nt], al, w.x, w.y);
                mma16f(cst[nt], ah, w.z, w.w);
            }
        }

        u64 cA[8], cB[8];
#pragma unroll
        for (int nt = 0; nt < 8; nt++) {
            int col0 = nt * 8 + 2 * tig;
            u64 b2p = LD2(&s_b2[col0]);
            cA[nt] = ADD2(F2(cst[nt][0], cst[nt][1]), b2p);
            cB[nt] = ADD2(F2(cst[nt][2], cst[nt][3]), b2p);
        }
        u64 sa = cA[0], sb = cB[0];
#pragma unroll
        for (int nt = 1; nt < 8; nt++) { sa = ADD2(sa, cA[nt]); sb = ADD2(sb, cB[nt]); }
        float s0, s1;
        UNPK(sa, s0, s1); float mA = qsum(s0 + s1) * 0.015625f;
        UNPK(sb, s0, s1); float mB = qsum(s0 + s1) * 0.015625f;
        u64 mA2 = F2(-mA, -mA), mB2 = F2(-mB, -mB);
        u64 qa = F2(0.f, 0.f), qb = F2(0.f, 0.f);
#pragma unroll
        for (int nt = 0; nt < 8; nt++) {
            cA[nt] = ADD2(cA[nt], mA2); qa = FMA2(cA[nt], cA[nt], qa);
            cB[nt] = ADD2(cB[nt], mB2); qb = FMA2(cB[nt], cB[nt], qb);
        }
        UNPK(qa, s0, s1); float rA = rsqrtf(qsum(s0 + s1) * 0.015625f + 1e-5f);
        UNPK(qb, s0, s1); float rB = rsqrtf(qsum(s0 + s1) * 0.015625f + 1e-5f);
        u64 rA2 = F2(rA, rA), rB2 = F2(rB, rB);

        u64 accA = F2(0.f, 0.f), accB = F2(0.f, 0.f);
#pragma unroll
        for (int nt = 0; nt < 8; nt++) {
            int col0 = nt * 8 + 2 * tig;
            u64 g2 = LD2(&s_g2[col0]), be2 = LD2(&s_be2[col0]);
            u64 zA = fast_gelu2(FMA2(MUL2(cA[nt], rA2), g2, be2));
            u64 zB = fast_gelu2(FMA2(MUL2(cB[nt], rB2), g2, be2));
            float z0, z1;
            UNPK(zA, z0, z1);
            accA = FMA2(F2(z0, z0), LD2(&s_w3[2 * col0]), accA);
            accA = FMA2(F2(z1, z1), LD2(&s_w3[2 * col0 + 2]), accA);
            UNPK(zB, z0, z1);
            accB = FMA2(F2(z0, z0), LD2(&s_w3[2 * col0]), accB);
            accB = FMA2(F2(z1, z1), LD2(&s_w3[2 * col0 + 2]), accB);
        }
        float px, py;
        UNPK(accA, px, py); float pA0 = qsum(px), pA1 = qsum(py);
        UNPK(accB, px, py); float pB0 = qsum(px), pB1 = qsum(py);

        if (tig == 0) {
            float tA0 = pA0 + b3_0, tA1 = pA1 + b3_1;
            float tB0 = pB0 + b3_0, tB1 = pB1 + b3_1;
            if (iA < 1000) {
                g_targets[(b * 1000 + iA) * 2]     = tA0;
                g_targets[(b * 1000 + iA) * 2 + 1] = tA1;
                smAcc += sl1(tA0 - ex) + sl1(tA1 - ey);
            }
            if (iB < 1000) {
                g_targets[(b * 1000 + iB) * 2]     = tB0;
                g_targets[(b * 1000 + iB) * 2 + 1] = tB1;
                smAcc += sl1(tB0 - ex) + sl1(tB1 - ey);
            }
        }
    }

    s_red[tid] = smAcc;
    __syncthreads();
#pragma unroll
    for (int s = 128; s > 0; s >>= 1) {
        if (tid < s) s_red[tid] += s_red[tid + s];
        __syncthreads();
    }
    if (tid == 0) g_off_part[b * 4 + blockIdx.x] = s_red[0];

    // ---- per-batch arrival; last block runs this batch's finalize ----
    __threadfence();
    __syncthreads();
    if (tid == 0) {
        int prev = atomicAdd(&g_bdone[b], 1);
        s_flag = (prev == 3);
    }
    __syncthreads();
    if (!s_flag) return;
    __threadfence();

    // ================= finalize (256 threads, 8 warps) =================
    float* s_t  = reinterpret_cast<float*>(dsm);
    float* s_p  = s_t + 2000;
    float* s_pd = s_p + 2000;
    u64*   s_key = reinterpret_cast<u64*>(dsm + 20096);

    for (int i = tid; i < 2000; i += 256) {
        s_t[i] = g_targets[b * 2000 + i];
        s_p[i] = g_pts[b * 2000 + i];
    }
    __syncthreads();

    // mean
    float a0 = 0.f, a1 = 0.f;
    for (int i = tid; i < 1000; i += 256) { a0 += s_t[2 * i]; a1 += s_t[2 * i + 1]; }
    a0 = wsum(a0); a1 = wsum(a1);
    if (lane == 0) { s_w[wid] = a0; s_w[8 + wid] = a1; }
    __syncthreads();
    if (tid < 32) {
        float v = (lane < 16) ? s_w[lane] : 0.f;
        v += __shfl_xor_sync(0xffffffffu, v, 4);
        v += __shfl_xor_sync(0xffffffffu, v, 2);
        v += __shfl_xor_sync(0xffffffffu, v, 1);
        if (lane == 0) s_bc[0] = v * 0.001f;
        if (lane == 8) s_bc[1] = v * 0.001f;
    }
    __syncthreads();
    float m0 = s_bc[0], m1 = s_bc[1];

    // var (ddof=1)
    float q0 = 0.f, q1 = 0.f;
    for (int i = tid; i < 1000; i += 256) {
        float d0 = s_t[2 * i] - m0, d1 = s_t[2 * i + 1] - m1;
        q0 += d0 * d0; q1 += d1 * d1;
    }
    q0 = wsum(q0); q1 = wsum(q1);
    if (lane == 0) { s_w[wid] = q0; s_w[8 + wid] = q1; }
    __syncthreads();
    if (tid < 32) {
        float v = (lane < 16) ? s_w[lane] : 0.f;
        v += __shfl_xor_sync(0xffffffffu, v, 4);
        v += __shfl_xor_sync(0xffffffffu, v, 2);
        v += __shfl_xor_sync(0xffffffffu, v, 1);
        if (lane == 0) s_bc[2] = v / 999.0f;
        if (lane == 8) s_bc[3] = v / 999.0f;
    }
    __syncthreads();
    float v0 = s_bc[2], v1 = s_bc[3];

    // policy_dist
    float den0 = sqrtf(6.2831853071795864f * v0 + 1e-6f);
    float den1 = sqrtf(6.2831853071795864f * v1 + 1e-6f);
    for (int i = tid; i < 1024; i += 256) {
        float pd = -1.0f;
        if (i < 1000) {
            float dx = s_t[2 * i] - m0, dy = s_t[2 * i + 1] - m1;
            float pdx = expf(-0.5f * dx * dx / v0 + 1e-6f) / den0;
            float pdy = expf(-0.5f * dy * dy / v1 + 1e-6f) / den1;
            pd = pdx * pdy;
        }
        s_pd[i] = pd;
    }
    __syncthreads();

    // max(pd)
    float mx = -1.0f;
    for (int i = tid; i < 1000; i += 256) mx = fmaxf(mx, s_pd[i]);
#pragma unroll
    for (int o = 16; o; o >>= 1) mx = fmaxf(mx, __shfl_xor_sync(0xffffffffu, mx, o));
    if (lane == 0) s_w[wid] = mx;
    __syncthreads();
    if (tid < 32) {
        float v = (lane < 8) ? s_w[lane] : -3.4e38f;
        v = fmaxf(v, __shfl_xor_sync(0xffffffffu, v, 4));
        v = fmaxf(v, __shfl_xor_sync(0xffffffffu, v, 2));
        v = fmaxf(v, __shfl_xor_sync(0xffffffffu, v, 1));
        if (lane == 0) s_bc[4] = v;
    }
    __syncthreads();
    mx = s_bc[4];

    // sum exp(pd - mx)
    float se = 0.f;
    for (int i = tid; i < 1000; i += 256) se += expf(s_pd[i] - mx);
    se = wsum(se);
    if (lane == 0) s_w[wid] = se;
    __syncthreads();
    if (tid < 32) {
        float v = (lane < 8) ? s_w[lane] : 0.f;
        v += __shfl_xor_sync(0xffffffffu, v, 4);
        v += __shfl_xor_sync(0xffffffffu, v, 2);
        v += __shfl_xor_sync(0xffffffffu, v, 1);
        if (lane == 0) s_bc[5] = v;
    }
    __syncthreads();
    float lse = mx + logf(s_bc[5]);

    // argmin distance to end (first-index tiebreak)
    float bd = 3.4e38f; int bi = 0x7fffffff;
    for (int i = tid; i < 1000; i += 256) {
        float dx = s_p[2 * i] - ex;
        float dy = s_p[2 * i + 1] - ey;
        float ds = sqrtf(dx * dx + dy * dy);
        if (ds < bd || (ds == bd && i < bi)) { bd = ds; bi = i; }
    }
#pragma unroll
    for (int o = 16; o; o >>= 1) {
        float od = __shfl_xor_sync(0xffffffffu, bd, o);
        int   oi = __shfl_xor_sync(0xffffffffu, bi, o);
        if (od < bd || (od == bd && oi < bi)) { bd = od; bi = oi; }
    }
    if (lane == 0) { s_w[wid] = bd; s_wi[wid] = bi; }
    __syncthreads();
    if (tid < 32) {
        float v  = (lane < 8) ? s_w[lane]  : 3.4e38f;
        int   vi = (lane < 8) ? s_wi[lane] : 0x7fffffff;
#pragma unroll
        for (int o = 4; o; o >>= 1) {
            float od = __shfl_xor_sync(0xffffffffu, v, o);
            int   oi = __shfl_xor_sync(0xffffffffu, vi, o);
            if (od < v || (od == v && oi < vi)) { v = od; vi = oi; }
        }
        if (lane == 0) s_bi = vi;
    }
    __syncthreads();
    float picked = s_pd[s_bi];

    // top-50: each warp sorts 2 windows of 64 descending, then tournament merge
#pragma unroll 1
    for (int wnd = 0; wnd < 2; wnd++) {
        int base = (2 * wid + wnd) * 64;
        int i0 = base + lane, i1 = i0 + 32;
        u64 k0 = (i0 < 1000) ? ((((u64)__float_as_uint(s_pd[i0])) << 32) | (u32)(~i0)) : 0ull;
        u64 k1 = (i1 < 1000) ? ((((u64)__float_as_uint(s_pd[i1])) << 32) | (u32)(~i1)) : 0ull;
#pragma unroll
        for (int k = 2; k <= 64; k <<= 1) {
#pragma unroll
            for (int j = k >> 1; j > 0; j >>= 1) {
                if (j == 32) {
                    u64 mxk = k0 > k1 ? k0 : k1;
                    u64 mnk = k0 > k1 ? k1 : k0;
                    k0 = mxk; k1 = mnk;
                } else {
                    u64 o0 = __shfl_xor_sync(0xffffffffu, k0, j);
                    u64 o1 = __shfl_xor_sync(0xffffffffu, k1, j);
                    bool low = (lane & j) == 0;
                    bool d0 = (lane & k) == 0;
                    bool d1 = (((lane + 32) & k) == 0);
                    bool t0 = (low == d0), t1 = (low == d1);
                    k0 = t0 ? (k0 > o0 ? k0 : o0) : (k0 < o0 ? k0 : o0);
                    k1 = t1 ? (k1 > o1 ? k1 : o1) : (k1 < o1 ? k1 : o1);
                }
            }
        }
        s_key[base + lane] = k0;
        s_key[base + 32 + lane] = k1;
    }
    __syncthreads();
    u64 k0 = 0, k1 = 0;
#pragma unroll
    for (int act = 8; act >= 1; act >>= 1) {
        if (wid < act) {
            u64 a0k = s_key[(2 * wid) * 64 + lane];
            u64 a1k = s_key[(2 * wid) * 64 + 32 + lane];
            u64 b0k = s_key[(2 * wid + 1) * 64 + 63 - lane];
            u64 b1k = s_key[(2 * wid + 1) * 64 + 31 - lane];
            k0 = a0k > b0k ? a0k : b0k;
            k1 = a1k > b1k ? a1k : b1k;
            { u64 mxk = k0 > k1 ? k0 : k1, mnk = k0 > k1 ? k1 : k0; k0 = mxk; k1 = mnk; }
#pragma unroll
            for (int j = 16; j > 0; j >>= 1) {
                u64 o0 = __shfl_xor_sync(0xffffffffu, k0, j);
                u64 o1 = __shfl_xor_sync(0xffffffffu, k1, j);
                bool tm = (lane & j) == 0;
                k0 = tm ? (k0 > o0 ? k0 : o0) : (k0 < o0 ? k0 : o0);
                k1 = tm ? (k1 > o1 ? k1 : o1) : (k1 < o1 ? k1 : o1);
            }
        }
        __syncthreads();
        if (act > 1 && wid < act) {
            s_key[wid * 64 + lane] = k0;
            s_key[wid * 64 + 32 + lane] = k1;
        }
        __syncthreads();
    }

    if (wid == 0) {
        float* outp = g_outbuf;
        float es = 0.f;
        u32 id = ~(u32)k0;
        float t0 = s_t[2 * id], t1 = s_t[2 * id + 1];
        outp[2 + (b * 50 + lane) * 2]     = t0;
        outp[2 + (b * 50 + lane) * 2 + 1] = t1;
        es = sl1(t0 - ex) + sl1(t1 - ey);
        if (lane < 18) {
            u32 id2 = ~(u32)k1;
            float u0 = s_t[2 * id2], u1 = s_t[2 * id2 + 1];
            int pos = 32 + lane;
            outp[2 + (b * 50 + pos) * 2]     = u0;
            outp[2 + (b * 50 + pos) * 2 + 1] = u1;
            es += sl1(u0 - ex) + sl1(u1 - ey);
        }
        es = wsum(es);
        if (lane == 0) {
            g_cls[b] = lse - picked;
            g_endsum[b] = es;
        }
    }
}

// ---------------- K4: final scalar reductions ----------------
__global__ void __launch_bounds__(512) reduce_kernel(float* __restrict__ out) {
    __shared__ float r[512];
    int tid = threadIdx.x;
    float offs = 0.f;
    for (int i = tid; i < 2048; i += 512) offs += g_off_part[i];
    float cls = g_cls[tid];
    float ends = g_endsum[tid];

    r[tid] = offs; __syncthreads();
    for (int s = 256; s > 0; s >>= 1) { if (tid < s) r[tid] += r[tid + s]; __syncthreads(); }
    float offT = r[0]; __syncthreads();
    r[tid] = cls; __syncthreads();
    for (int s = 256; s > 0; s >>= 1) { if (tid < s) r[tid] += r[tid + s]; __syncthreads(); }
    float clsT = r[0]; __syncthreads();
    r[tid] = ends; __syncthreads();
    for (int s = 256; s > 0; s >>= 1) { if (tid < s) r[tid] += r[tid + s]; __syncthreads(); }
    float endT = r[0];

    if (tid == 0) {
        out[0] = clsT / 512.0f;
        out[1] = offT / 1024000.0f + 3.0f * (endT / 51200.0f);
    }
}

extern "C" void kernel_launch(void* const* d_in, const int* in_sizes, int n_in,
                              void* d_out, int out_size) {
    const float* osm   = (const float*)d_in[0];
    const float* at    = (const float*)d_in[1];
    const float* vf    = (const float*)d_in[2];
    const float* end   = (const float*)d_in[3];
    const float* ox_w1 = (const float*)d_in[5];
    const float* ox_b1 = (const float*)d_in[6];
    const float* ox_g1 = (const float*)d_in[7];
    const float* ox_be1= (const float*)d_in[8];
    const float* ox_w2 = (const float*)d_in[9];
    const float* ox_b2 = (const float*)d_in[10];
    const float* tp_w1 = (const float*)d_in[11];
    const float* tp_b1 = (const float*)d_in[12];
    const float* tp_g1 = (const float*)d_in[13];
    const float* tp_be1= (const float*)d_in[14];
    const float* tp_w2 = (const float*)d_in[15];
    const float* tp_b2 = (const float*)d_in[16];
    const float* tp_g2 = (const float*)d_in[17];
    const float* tp_be2= (const float*)d_in[18];
    const float* tp_w3 = (const float*)d_in[19];
    const float* tp_b3 = (const float*)d_in[20];
    float* out = (float*)d_out;

    set_outbuf_kernel<<<1, 1>>>(out);
    setup_kernel<<<512, 1024>>>(osm, at, vf, ox_w1, ox_b1, tp_w1, tp_b1, tp_w2);
    dim3 g(4, 512);
    mlp_kernel<<<g, 256, MLP_DSMEM>>>(ox_w1, ox_g1, ox_be1, ox_w2, ox_b2,
                                      tp_w1, tp_g1, tp_be1, tp_w2, tp_b2,
                                      tp_g2, tp_be2, tp_w3, tp_b3, end);
    reduce_kernel<<<1, 512>>>(out);
}

// round 17
// speedup vs baseline: 1.0455x; 1.0455x over previous
#include <cuda_runtime.h>
#include <cuda_fp16.h>
#include <cuda_bf16.h>
#include <cstdint>

typedef unsigned long long u64;
typedef unsigned int u32;

// ---------------- scratch ----------------
__device__ float g_pre_ox[512 * 64];
__device__ float g_pre_tp[512 * 64];
__device__ float g_stats[512 * 18];
__device__ float g_pts[512 * 1000 * 2];
__device__ float g_targets[512 * 1000 * 2];
__device__ float g_off_part[512 * 4];
__device__ float g_cls[512];
__device__ float g_endsum[512];
__device__ uint4 g_w4[16 * 64];   // W2 fp16 hi/lo fragments, dense b-frag layout

// ---------------- packed f32x2 helpers ----------------
__device__ __forceinline__ u64 F2(float a, float b) {
    u64 r; asm("mov.b64 %0,{%1,%2};" : "=l"(r) : "f"(a), "f"(b)); return r;
}
__device__ __forceinline__ void UNPK(u64 v, float& a, float& b) {
    asm("mov.b64 {%0,%1},%2;" : "=f"(a), "=f"(b) : "l"(v));
}
__device__ __forceinline__ u64 FMA2(u64 a, u64 b, u64 c) {
    u64 d; asm("fma.rn.f32x2 %0,%1,%2,%3;" : "=l"(d) : "l"(a), "l"(b), "l"(c)); return d;
}
__device__ __forceinline__ u64 ADD2(u64 a, u64 b) {
    u64 d; asm("add.rn.f32x2 %0,%1,%2;" : "=l"(d) : "l"(a), "l"(b)); return d;
}
__device__ __forceinline__ u64 MUL2(u64 a, u64 b) {
    u64 d; asm("mul.rn.f32x2 %0,%1,%2;" : "=l"(d) : "l"(a), "l"(b)); return d;
}
__device__ __forceinline__ u64 LD2(const float* p) {
    return *reinterpret_cast<const u64*>(p);
}
__device__ __forceinline__ u64 C2(float c) { return F2(c, c); }

__device__ __forceinline__ float sl1(float z) {
    float d = fabsf(z);
    return d < 1.0f ? 0.5f * d * d : d - 0.5f;
}

// Packed branchless exact-GELU (A&S 7.1.26 erfc, -0.5 folded into coefficients).
__device__ __forceinline__ u64 fast_gelu2(u64 z2) {
    u64 az = z2 & 0x7fffffff7fffffffull;
    u64 u2 = MUL2(az, C2(0.70710678118654752f));
    u64 dn = FMA2(u2, C2(0.3275911f), C2(1.0f));
    float d0, d1; UNPK(dn, d0, d1);
    float t0, t1;
    asm("rcp.approx.f32 %0, %1;" : "=f"(t0) : "f"(d0));
    asm("rcp.approx.f32 %0, %1;" : "=f"(t1) : "f"(d1));
    u64 t2 = F2(t0, t1);
    u64 gg = MUL2(MUL2(u2, u2), C2(-1.4426950408889634f));
    float g0, g1; UNPK(gg, g0, g1);
    float e0, e1;
    asm("ex2.approx.f32 %0, %1;" : "=f"(e0) : "f"(g0));
    asm("ex2.approx.f32 %0, %1;" : "=f"(e1) : "f"(g1));
    u64 p2 = FMA2(t2, C2(-0.5307027145f), C2(0.7265760135f));
    p2 = FMA2(p2, t2, C2(-0.7107068705f));
    p2 = FMA2(p2, t2, C2(0.142248368f));
    p2 = FMA2(p2, t2, C2(-0.127414796f));
    u64 q2 = MUL2(MUL2(p2, t2), F2(e0, e1));
    float z0, z1; UNPK(z2, z0, z1);
    u64 rl = F2(fmaxf(z0, 0.f), fmaxf(z1, 0.f));
    return FMA2(az, q2, rl);
}

// split f32 pair -> f16x2 hi + f16x2 residual lo
__device__ __forceinline__ void hsplit(u64 xy, u32& h, u32& l) {
    float x, y; UNPK(xy, x, y);
    __half2 hh = __floats2half2_rn(x, y);
    h = *reinterpret_cast<u32*>(&hh);
    float2 bk = __half22float2(hh);
    __half2 hl = __floats2half2_rn(x - bk.x, y - bk.y);
    l = *reinterpret_cast<u32*>(&hl);
}

// m16n8k16 fp16 MMA, f32 accum, D += A*B
__device__ __forceinline__ void mma16f(float* c, const u32* a, u32 b0, u32 b1) {
    asm volatile(
        "mma.sync.aligned.m16n8k16.row.col.f32.f16.f16.f32 "
        "{%0,%1,%2,%3},{%4,%5,%6,%7},{%8,%9},{%0,%1,%2,%3};"
        : "+f"(c[0]), "+f"(c[1]), "+f"(c[2]), "+f"(c[3])
        : "r"(a[0]), "r"(a[1]), "r"(a[2]), "r"(a[3]), "r"(b0), "r"(b1));
}

__device__ __forceinline__ float qsum(float v) {
    v += __shfl_xor_sync(0xffffffffu, v, 1);
    v += __shfl_xor_sync(0xffffffffu, v, 2);
    return v;
}
__device__ __forceinline__ float wsum(float v) {
#pragma unroll
    for (int o = 16; o; o >>= 1) v += __shfl_xor_sync(0xffffffffu, v, o);
    return v;
}

// Closed-form LN (stats precomputed) + packed GELU on two fragment rows.
__device__ __forceinline__ void ln_gelu_closed(u64* hA, u64* hB,
                                               float mA, float rA, float mB, float rB,
                                               const float* gp, const float* bep, int tig) {
    u64 rA2 = C2(rA), rB2 = C2(rB);
    u64 nmrA = C2(-mA * rA), nmrB = C2(-mB * rB);
#pragma unroll
    for (int j = 0; j < 8; j++) {
        int o = 8 * j + 2 * tig;
        u64 g2 = LD2(&gp[o]), be2 = LD2(&bep[o]);
        u64 offA = FMA2(nmrA, g2, be2);
        u64 offB = FMA2(nmrB, g2, be2);
        hA[j] = fast_gelu2(FMA2(hA[j], MUL2(rA2, g2), offA));
        hB[j] = fast_gelu2(FMA2(hB[j], MUL2(rB2, g2), offB));
    }
}

// ---------------- K1: FUSED setup = precompute + stats + W2 conversion + hybrid bitonic select ----------------
__global__ void __launch_bounds__(1024) setup_kernel(
    const float* __restrict__ osm,
    const float* __restrict__ at, const float* __restrict__ vf,
    const float* __restrict__ ox_w1, const float* __restrict__ ox_b1,
    const float* __restrict__ tp_w1, const float* __restrict__ tp_b1,
    const float* __restrict__ tp_w2) {
    __shared__ u64 s[2048];
    __shared__ float s_vf[64], s_at[64];
    __shared__ float pa[4][64], pt[4][64];
    __shared__ float s_pox[64], s_ptp[64];

    int b = blockIdx.x, t = threadIdx.x;
    int wd = t >> 5, lane = t & 31;

    u64 k0, k1;
    {
        int m0 = 64 * wd + lane, m1 = m0 + 32;
        float x = osm[(b * 2000 + m0) * 4];
        float y = osm[(b * 2000 + m0) * 4 + 1];
        k0 = (m0 < 2000) ? (((u64)__float_as_uint(x * x + y * y) << 32) | (u32)m0) : ~0ull;
        if (m1 < 2000) {
            float x1 = osm[(b * 2000 + m1) * 4];
            float y1 = osm[(b * 2000 + m1) * 4 + 1];
            k1 = ((u64)__float_as_uint(x1 * x1 + y1 * y1) << 32) | (u32)m1;
        } else k1 = ~0ull;
    }

    if (b == 0) {
#pragma unroll
        for (int i = t; i < 2048; i += 1024) {
            int kp = i >> 6, n = i & 63;
            float w0 = tp_w2[(2 * kp) * 64 + n];
            float w1 = tp_w2[(2 * kp + 1) * 64 + n];
            __half2 hh = __floats2half2_rn(w0, w1);
            u32 hi = *reinterpret_cast<u32*>(&hh);
            float2 bk = __half22float2(hh);
            __half2 hl = __floats2half2_rn(w0 - bk.x, w1 - bk.y);
            u32 lo = *reinterpret_cast<u32*>(&hl);
            int kt = kp >> 3, rem = kp & 7;
            int row = kt * 4 + (rem & 3);
            int second = rem >> 2;
            u32* base = reinterpret_cast<u32*>(&g_w4[row * 64 + n]);
            base[second]     = hi;
            base[2 + second] = lo;
        }
    }

    if (t < 64) { s_vf[t] = vf[b * 64 + t]; s_at[t] = at[b * 64 + t]; }
    __syncthreads();
    if (t < 256) {
        int c = t & 63, kq = t >> 6;
        float a = 0.f, tt = 0.f;
#pragma unroll
        for (int k = kq * 16; k < kq * 16 + 16; k++) {
            a  += s_vf[k] * ox_w1[k * 64 + c] + s_at[k] * ox_w1[(64 + k) * 64 + c];
            tt += s_vf[k] * tp_w1[k * 64 + c] + s_at[k] * tp_w1[(64 + k) * 64 + c];
        }
        pa[kq][c] = a; pt[kq][c] = tt;
    }
    __syncthreads();
    if (t < 64) {
        float pox = pa[0][t] + pa[1][t] + pa[2][t] + pa[3][t] + ox_b1[t];
        float ptp = pt[0][t] + pt[1][t] + pt[2][t] + pt[3][t] + tp_b1[t];
        g_pre_ox[b * 64 + t] = pox;
        g_pre_tp[b * 64 + t] = ptp;
        s_pox[t] = pox; s_ptp[t] = ptp;
    }
    __syncthreads();
    if (wd < 2) {
        const float* pre = (wd == 0) ? s_pox : s_ptp;
        const float* w1  = (wd == 0) ? ox_w1 : tp_w1;
        float p0 = pre[2 * lane],           p1 = pre[2 * lane + 1];
        float x0 = w1[128 * 64 + 2 * lane], x1 = w1[128 * 64 + 2 * lane + 1];
        float y0 = w1[129 * 64 + 2 * lane], y1 = w1[129 * 64 + 2 * lane + 1];
        float v[9];
        v[0] = p0 + p1;           v[1] = x0 + x1;           v[2] = y0 + y1;
        v[3] = p0 * p0 + p1 * p1; v[4] = x0 * x0 + x1 * x1; v[5] = y0 * y0 + y1 * y1;
        v[6] = p0 * x0 + p1 * x1; v[7] = p0 * y0 + p1 * y1; v[8] = x0 * y0 + x1 * y1;
#pragma unroll
        for (int k = 0; k < 9; k++) v[k] = wsum(v[k]);
        if (lane == 0) {
#pragma unroll
            for (int k = 0; k < 9; k++)
                g_stats[b * 18 + wd * 9 + k] = v[k] * 0.015625f * (k >= 6 ? 2.0f : 1.0f);
        }
    }

    // phase 1: per-warp register bitonic, k=2..64
#pragma unroll
    for (int k = 2; k <= 32; k <<= 1) {
#pragma unroll
        for (int j = k >> 1; j > 0; j >>= 1) {
            u64 o0 = __shfl_xor_sync(0xffffffffu, k0, j);
            u64 o1 = __shfl_xor_sync(0xffffffffu, k1, j);
            bool low = (lane & j) == 0;
            bool up0 = (lane & k) == 0;
            bool up1 = ((lane + 32) & k) == 0;
            bool t0 = (low != up0), t1 = (low != up1);
            k0 = t0 ? (k0 > o0 ? k0 : o0) : (k0 < o0 ? k0 : o0);
            k1 = t1 ? (k1 > o1 ? k1 : o1) : (k1 < o1 ? k1 : o1);
        }
    }
    {
        bool up = ((wd & 1) == 0);
        u64 lo = k0 < k1 ? k0 : k1, hi = k0 < k1 ? k1 : k0;
        k0 = up ? lo : hi; k1 = up ? hi : lo;
#pragma unroll
        for (int j = 16; j > 0; j >>= 1) {
            u64 o0 = __shfl_xor_sync(0xffffffffu, k0, j);
            u64 o1 = __shfl_xor_sync(0xffffffffu, k1, j);
            bool low = (lane & j) == 0;
            bool tk = (low != up);
            k0 = tk ? (k0 > o0 ? k0 : o0) : (k0 < o0 ? k0 : o0);
            k1 = tk ? (k1 > o1 ? k1 : o1) : (k1 < o1 ? k1 : o1);
        }
    }
    s[64 * wd + lane] = k0;
    s[64 * wd + 32 + lane] = k1;

    // phase 2: k=128..2048; j>=64 smem, j<=32 register tail
#pragma unroll 1
    for (int k = 128; k <= 2048; k <<= 1) {
#pragma unroll 1
        for (int j = k >> 1; j >= 64; j >>= 1) {
            __syncthreads();
            int i0 = ((t & ~(j - 1)) << 1) | (t & (j - 1));
            int i1 = i0 | j;
            bool up = ((i0 & k) == 0);
            u64 A = s[i0], B = s[i1];
            if ((A > B) == up) { s[i0] = B; s[i1] = A; }
        }
        __syncthreads();
        k0 = s[64 * wd + lane];
        k1 = s[64 * wd + 32 + lane];
        bool up = (((wd << 6) & k) == 0);
        {
            u64 lo = k0 < k1 ? k0 : k1, hi = k0 < k1 ? k1 : k0;
            k0 = up ? lo : hi; k1 = up ? hi : lo;
        }
#pragma unroll
        for (int j = 16; j > 0; j >>= 1) {
            u64 o0 = __shfl_xor_sync(0xffffffffu, k0, j);
            u64 o1 = __shfl_xor_sync(0xffffffffu, k1, j);
            bool low = (lane & j) == 0;
            bool tk = (low != up);
            k0 = tk ? (k0 > o0 ? k0 : o0) : (k0 < o0 ? k0 : o0);
            k1 = tk ? (k1 > o1 ? k1 : o1) : (k1 < o1 ? k1 : o1);
        }
        s[64 * wd + lane] = k0;
        s[64 * wd + 32 + lane] = k1;
    }
    __syncthreads();

    if (t < 1000) {
        u32 m = (u32)(s[t] & 0xffffffffull);
        g_pts[(b * 1000 + t) * 2]     = osm[(b * 2000 + m) * 4];
        g_pts[(b * 1000 + t) * 2 + 1] = osm[(b * 2000 + m) * 4 + 1];
    }
}

// ---------------- K2: per-point MLP (unchanged from 186.9us best) ----------------
#define W4STR 66
#define MLP_DSMEM (16 * W4STR * 16)

#define T_PRE_OX 0
#define T_OXX    1
#define T_OXY    2
#define T_OXG    3
#define T_OXBE   4
#define T_W2A    5
#define T_W2B    6
#define T_PRE_TP 7
#define T_TPX    8
#define T_TPY    9
#define T_G1     10
#define T_BE1    11

__global__ void __launch_bounds__(256, 3) mlp_kernel(
    const float* __restrict__ ox_w1, const float* __restrict__ ox_g1, const float* __restrict__ ox_be1,
    const float* __restrict__ ox_w2, const float* __restrict__ ox_b2,
    const float* __restrict__ tp_w1, const float* __restrict__ tp_g1, const float* __restrict__ tp_be1,
    const float* __restrict__ tp_w2, const float* __restrict__ tp_b2,
    const float* __restrict__ tp_g2, const float* __restrict__ tp_be2,
    const float* __restrict__ tp_w3, const float* __restrict__ tp_b3,
    const float* __restrict__ end) {
    extern __shared__ uint4 w4[];
    __shared__ __align__(16) float P[12][64];
    __shared__ __align__(16) float s_b2[64], s_g2[64], s_be2[64], s_w3[128];
    __shared__ float s_red[256];
    __shared__ float s_st[18];

    int b = blockIdx.y;
    int tid = threadIdx.x;
    int wid = tid >> 5, lane = tid & 31;

    if (tid < 64) {
        P[T_PRE_OX][tid] = g_pre_ox[b * 64 + tid];
        P[T_PRE_TP][tid] = g_pre_tp[b * 64 + tid];
        P[T_OXX][tid] = ox_w1[128 * 64 + tid];
        P[T_OXY][tid] = ox_w1[129 * 64 + tid];
        P[T_TPX][tid] = tp_w1[128 * 64 + tid];
        P[T_TPY][tid] = tp_w1[129 * 64 + tid];
        P[T_OXG][tid] = ox_g1[tid];
        P[T_OXBE][tid] = ox_be1[tid];
        P[T_G1][tid] = tp_g1[tid];
        P[T_BE1][tid] = tp_be1[tid];
        P[T_W2A][tid] = ox_w2[2 * tid];
        P[T_W2B][tid] = ox_w2[2 * tid + 1];
        s_b2[tid] = tp_b2[tid]; s_g2[tid] = tp_g2[tid]; s_be2[tid] = tp_be2[tid];
    }
    if (tid < 128) s_w3[tid] = tp_w3[tid];
    if (tid >= 128 && tid < 146) s_st[tid - 128] = g_stats[b * 18 + tid - 128];
#pragma unroll
    for (int i = tid; i < 1024; i += 256) {
        w4[(i >> 6) * W4STR + (i & 63)] = g_w4[i];
    }
    __syncthreads();

    int gid = lane >> 2, tig = lane & 3;
    float ex = end[2 * b], ey = end[2 * b + 1];
    float b2o0 = ox_b2[0], b2o1 = ox_b2[1];
    float b3_0 = tp_b3[0], b3_1 = tp_b3[1];
    float smAcc = 0.f;

#pragma unroll 1
    for (int mt = 0; mt < 2; mt++) {
        int iA = blockIdx.x * 256 + wid * 32 + mt * 16 + gid;
        int iB = iA + 8;
        float xA = 0.f, yA = 0.f, xB = 0.f, yB = 0.f;
        if (iA < 1000) { float2 v = *reinterpret_cast<const float2*>(&g_pts[(b * 1000 + iA) * 2]); xA = v.x; yA = v.y; }
        if (iB < 1000) { float2 v = *reinterpret_cast<const float2*>(&g_pts[(b * 1000 + iB) * 2]); xB = v.x; yB = v.y; }

        u64 hA[8], hB[8];
        {
            u64 xA2 = F2(xA, xA), yA2 = F2(yA, yA), xB2 = F2(xB, xB), yB2 = F2(yB, yB);
#pragma unroll
            for (int j = 0; j < 8; j++) {
                int o = 8 * j + 2 * tig;
                u64 pre = LD2(&P[T_PRE_OX][o]), wx = LD2(&P[T_OXX][o]), wy = LD2(&P[T_OXY][o]);
                hA[j] = FMA2(yA2, wy, FMA2(xA2, wx, pre));
                hB[j] = FMA2(yB2, wy, FMA2(xB2, wx, pre));
            }
        }
        {
            float mA = fmaf(yA, s_st[2], fmaf(xA, s_st[1], s_st[0]));
            float mB = fmaf(yB, s_st[2], fmaf(xB, s_st[1], s_st[0]));
            float eA = fmaf(yA, fmaf(yA, s_st[5], s_st[7]),
                       fmaf(xA, fmaf(yA, s_st[8], fmaf(xA, s_st[4], s_st[6])), s_st[3]));
            float eB = fmaf(yB, fmaf(yB, s_st[5], s_st[7]),
                       fmaf(xB, fmaf(yB, s_st[8], fmaf(xB, s_st[4], s_st[6])), s_st[3]));
            float rA = rsqrtf(fmaf(-mA, mA, eA) + 1e-5f);
            float rB = rsqrtf(fmaf(-mB, mB, eB) + 1e-5f);
            ln_gelu_closed(hA, hB, mA, rA, mB, rB, &P[T_OXG][0], &P[T_OXBE][0], tig);
        }

        float txA, tyA, txB, tyB;
        {
            u64 axA = F2(0.f, 0.f), ayA = axA, axB = axA, ayB = axA;
#pragma unroll
            for (int j = 0; j < 8; j++) {
                int o = 8 * j + 2 * tig;
                u64 wa = LD2(&P[T_W2A][o]), wb = LD2(&P[T_W2B][o]);
                axA = FMA2(hA[j], wa, axA); ayA = FMA2(hA[j], wb, ayA);
                axB = FMA2(hB[j], wa, axB); ayB = FMA2(hB[j], wb, ayB);
            }
            float p0, p1;
            UNPK(axA, p0, p1); txA = xA + qsum(p0 + p1) + b2o0;
            UNPK(ayA, p0, p1); tyA = yA + qsum(p0 + p1) + b2o1;
            UNPK(axB, p0, p1); txB = xB + qsum(p0 + p1) + b2o0;
            UNPK(ayB, p0, p1); tyB = yB + qsum(p0 + p1) + b2o1;
        }

        {
            u64 xA2 = F2(txA, txA), yA2 = F2(tyA, tyA), xB2 = F2(txB, txB), yB2 = F2(tyB, tyB);
#pragma unroll
            for (int j = 0; j < 8; j++) {
                int o = 8 * j + 2 * tig;
                u64 pre = LD2(&P[T_PRE_TP][o]), wx = LD2(&P[T_TPX][o]), wy = LD2(&P[T_TPY][o]);
                hA[j] = FMA2(yA2, wy, FMA2(xA2, wx, pre));
                hB[j] = FMA2(yB2, wy, FMA2(xB2, wx, pre));
            }
        }
        {
            float mA = fmaf(tyA, s_st[11], fmaf(txA, s_st[10], s_st[9]));
            float mB = fmaf(tyB, s_st[11], fmaf(txB, s_st[10], s_st[9]));
            float eA = fmaf(tyA, fmaf(tyA, s_st[14], s_st[16]),
                       fmaf(txA, fmaf(tyA, s_st[17], fmaf(txA, s_st[13], s_st[15])), s_st[12]));
            float eB = fmaf(tyB, fmaf(tyB, s_st[14], s_st[16]),
                       fmaf(txB, fmaf(tyB, s_st[17], fmaf(txB, s_st[13], s_st[15])), s_st[12]));
            float rA = rsqrtf(fmaf(-mA, mA, eA) + 1e-5f);
            float rB = rsqrtf(fmaf(-mB, mB, eB) + 1e-5f);
            ln_gelu_closed(hA, hB, mA, rA, mB, rB, &P[T_G1][0], &P[T_BE1][0], tig);
        }

        float cst[8][4];
#pragma unroll
        for (int nt = 0; nt < 8; nt++)
#pragma unroll
            for (int qq = 0; qq < 4; qq++) cst[nt][qq] = 0.f;

#pragma unroll
        for (int kt = 0; kt < 4; kt++) {
            u32 ah[4], al[4];
            hsplit(hA[2 * kt],     ah[0], al[0]);
            hsplit(hB[2 * kt],     ah[1], al[1]);
            hsplit(hA[2 * kt + 1], ah[2], al[2]);
            hsplit(hB[2 * kt + 1], ah[3], al[3]);
            const uint4* rp = &w4[(kt * 4 + tig) * W4STR];
#pragma unroll
            for (int nt = 0; nt < 8; nt++) {
                uint4 w = rp[8 * nt + gid];
                mma16f(cst[nt], ah, w.x, w.y);
                mma16f(cst[nt], al, w.x, w.y);
                mma16f(cst[nt], ah, w.z, w.w);
            }
        }

        u64 cA[8], cB[8];
#pragma unroll
        for (int nt = 0; nt < 8; nt++) {
            int col0 = nt * 8 + 2 * tig;
            u64 b2p = LD2(&s_b2[col0]);
            cA[nt] = ADD2(F2(cst[nt][0], cst[nt][1]), b2p);
            cB[nt] = ADD2(F2(cst[nt][2], cst[nt][3]), b2p);
        }
        u64 sa = cA[0], sb = cB[0];
#pragma unroll
        for (int nt = 1; nt < 8; nt++) { sa = ADD2(sa, cA[nt]); sb = ADD2(sb, cB[nt]); }
        float s0, s1;
        UNPK(sa, s0, s1); float mA = qsum(s0 + s1) * 0.015625f;
        UNPK(sb, s0, s1); float mB = qsum(s0 + s1) * 0.015625f;
        u64 mA2 = F2(-mA, -mA), mB2 = F2(-mB, -mB);
        u64 qa = F2(0.f, 0.f), qb = F2(0.f, 0.f);
#pragma unroll
        for (int nt = 0; nt < 8; nt++) {
            cA[nt] = ADD2(cA[nt], mA2); qa = FMA2(cA[nt], cA[nt], qa);
            cB[nt] = ADD2(cB[nt], mB2); qb = FMA2(cB[nt], cB[nt], qb);
        }
        UNPK(qa, s0, s1); float rA = rsqrtf(qsum(s0 + s1) * 0.015625f + 1e-5f);
        UNPK(qb, s0, s1); float rB = rsqrtf(qsum(s0 + s1) * 0.015625f + 1e-5f);
        u64 rA2 = F2(rA, rA), rB2 = F2(rB, rB);

        u64 accA = F2(0.f, 0.f), accB = F2(0.f, 0.f);
#pragma unroll
        for (int nt = 0; nt < 8; nt++) {
            int col0 = nt * 8 + 2 * tig;
            u64 g2 = LD2(&s_g2[col0]), be2 = LD2(&s_be2[col0]);
            u64 zA = fast_gelu2(FMA2(MUL2(cA[nt], rA2), g2, be2));
            u64 zB = fast_gelu2(FMA2(MUL2(cB[nt], rB2), g2, be2));
            float z0, z1;
            UNPK(zA, z0, z1);
            accA = FMA2(F2(z0, z0), LD2(&s_w3[2 * col0]), accA);
            accA = FMA2(F2(z1, z1), LD2(&s_w3[2 * col0 + 2]), accA);
            UNPK(zB, z0, z1);
            accB = FMA2(F2(z0, z0), LD2(&s_w3[2 * col0]), accB);
            accB = FMA2(F2(z1, z1), LD2(&s_w3[2 * col0 + 2]), accB);
        }
        float px, py;
        UNPK(accA, px, py); float pA0 = qsum(px), pA1 = qsum(py);
        UNPK(accB, px, py); float pB0 = qsum(px), pB1 = qsum(py);

        if (tig == 0) {
            float tA0 = pA0 + b3_0, tA1 = pA1 + b3_1;
            float tB0 = pB0 + b3_0, tB1 = pB1 + b3_1;
            if (iA < 1000) {
                g_targets[(b * 1000 + iA) * 2]     = tA0;
                g_targets[(b * 1000 + iA) * 2 + 1] = tA1;
                smAcc += sl1(tA0 - ex) + sl1(tA1 - ey);
            }
            if (iB < 1000) {
                g_targets[(b * 1000 + iB) * 2]     = tB0;
                g_targets[(b * 1000 + iB) * 2 + 1] = tB1;
                smAcc += sl1(tB0 - ex) + sl1(tB1 - ey);
            }
        }
    }

    s_red[tid] = smAcc;
    __syncthreads();
#pragma unroll
    for (int s = 128; s > 0; s >>= 1) {
        if (tid < s) s_red[tid] += s_red[tid + s];
        __syncthreads();
    }
    if (tid == 0) g_off_part[b * 4 + blockIdx.x] = s_red[0];
}

// ---------------- K3: per-batch stats, policy, top-50 (unchanged) ----------------
__global__ void __launch_bounds__(512) finalize_kernel(const float* __restrict__ end,
                                                       float* __restrict__ out) {
    __shared__ float s_t[2000];
    __shared__ float s_p[2000];
    __shared__ float s_pd[1024];
    __shared__ u64 s_key[1024];
    __shared__ float s_w[32];
    __shared__ int   s_wi[16];
    __shared__ float s_bc[8];
    __shared__ int s_bi;

    int b = blockIdx.x, tid = threadIdx.x;
    int wid = tid >> 5, lane = tid & 31;

    for (int i = tid; i < 2000; i += 512) {
        s_t[i] = g_targets[b * 2000 + i];
        s_p[i] = g_pts[b * 2000 + i];
    }
    __syncthreads();

    // mean
    float a0 = 0.f, a1 = 0.f;
    for (int i = tid; i < 1000; i += 512) { a0 += s_t[2 * i]; a1 += s_t[2 * i + 1]; }
    a0 = wsum(a0); a1 = wsum(a1);
    if (lane == 0) { s_w[wid] = a0; s_w[16 + wid] = a1; }
    __syncthreads();
    if (tid < 32) {
        float v = s_w[tid];
        v += __shfl_xor_sync(0xffffffffu, v, 8);
        v += __shfl_xor_sync(0xffffffffu, v, 4);
        v += __shfl_xor_sync(0xffffffffu, v, 2);
        v += __shfl_xor_sync(0xffffffffu, v, 1);
        if ((tid & 15) == 0) s_bc[tid >> 4] = v * 0.001f;
    }
    __syncthreads();
    float m0 = s_bc[0], m1 = s_bc[1];

    // var (ddof=1)
    float q0 = 0.f, q1 = 0.f;
    for (int i = tid; i < 1000; i += 512) {
        float d0 = s_t[2 * i] - m0, d1 = s_t[2 * i + 1] - m1;
        q0 += d0 * d0; q1 += d1 * d1;
    }
    q0 = wsum(q0); q1 = wsum(q1);
    if (lane == 0) { s_w[wid] = q0; s_w[16 + wid] = q1; }
    __syncthreads();
    if (tid < 32) {
        float v = s_w[tid];
        v += __shfl_xor_sync(0xffffffffu, v, 8);
        v += __shfl_xor_sync(0xffffffffu, v, 4);
        v += __shfl_xor_sync(0xffffffffu, v, 2);
        v += __shfl_xor_sync(0xffffffffu, v, 1);
        if ((tid & 15) == 0) s_bc[2 + (tid >> 4)] = v / 999.0f;
    }
    __syncthreads();
    float v0 = s_bc[2], v1 = s_bc[3];

    // policy_dist
    float den0 = sqrtf(6.2831853071795864f * v0 + 1e-6f);
    float den1 = sqrtf(6.2831853071795864f * v1 + 1e-6f);
    for (int i = tid; i < 1024; i += 512) {
        float pd = -1.0f;
        if (i < 1000) {
            float dx = s_t[2 * i] - m0, dy = s_t[2 * i + 1] - m1;
            float pdx = expf(-0.5f * dx * dx / v0 + 1e-6f) / den0;
            float pdy = expf(-0.5f * dy * dy / v1 + 1e-6f) / den1;
            pd = pdx * pdy;
        }
        s_pd[i] = pd;
    }
    __syncthreads();

    // max(pd)
    float mx = -1.0f;
    for (int i = tid; i < 1000; i += 512) mx = fmaxf(mx, s_pd[i]);
#pragma unroll
    for (int o = 16; o; o >>= 1) mx = fmaxf(mx, __shfl_xor_sync(0xffffffffu, mx, o));
    if (lane == 0) s_w[wid] = mx;
    __syncthreads();
    if (tid < 32) {
        float v = (tid < 16) ? s_w[tid] : -3.4e38f;
        v = fmaxf(v, __shfl_xor_sync(0xffffffffu, v, 8));
        v = fmaxf(v, __shfl_xor_sync(0xffffffffu, v, 4));
        v = fmaxf(v, __shfl_xor_sync(0xffffffffu, v, 2));
        v = fmaxf(v, __shfl_xor_sync(0xffffffffu, v, 1));
        if (tid == 0) s_bc[4] = v;
    }
    __syncthreads();
    mx = s_bc[4];

    // sum exp(pd - mx)
    float se = 0.f;
    for (int i = tid; i < 1000; i += 512) se += expf(s_pd[i] - mx);
    se = wsum(se);
    if (lane == 0) s_w[wid] = se;
    __syncthreads();
    if (tid < 32) {
        float v = (tid < 16) ? s_w[tid] : 0.0f;
        v += __shfl_xor_sync(0xffffffffu, v, 8);
        v += __shfl_xor_sync(0xffffffffu, v, 4);
        v += __shfl_xor_sync(0xffffffffu, v, 2);
        v += __shfl_xor_sync(0xffffffffu, v, 1);
        if (tid == 0) s_bc[5] = v;
    }
    __syncthreads();
    float lse = mx + logf(s_bc[5]);

    // argmin distance to end (first-index tiebreak)
    float ex = end[2 * b], ey = end[2 * b + 1];
    float bd = 3.4e38f; int bi = 0x7fffffff;
    for (int i = tid; i < 1000; i += 512) {
        float dx = s_p[2 * i] - ex;
        float dy = s_p[2 * i + 1] - ey;
        float ds = sqrtf(dx * dx + dy * dy);
        if (ds < bd || (ds == bd && i < bi)) { bd = ds; bi = i; }
    }
#pragma unroll
    for (int o = 16; o; o >>= 1) {
        float od = __shfl_xor_sync(0xffffffffu, bd, o);
        int   oi = __shfl_xor_sync(0xffffffffu, bi, o);
        if (od < bd || (od == bd && oi < bi)) { bd = od; bi = oi; }
    }
    if (lane == 0) { s_w[wid] = bd; s_wi[wid] = bi; }
    __syncthreads();
    if (tid < 32) {
        float v  = (tid < 16) ? s_w[tid]  : 3.4e38f;
        int   vi = (tid < 16) ? s_wi[tid] : 0x7fffffff;
#pragma unroll
        for (int o = 8; o; o >>= 1) {
            float od = __shfl_xor_sync(0xffffffffu, v, o);
            int   oi = __shfl_xor_sync(0xffffffffu, vi, o);
            if (od < v || (od == v && oi < vi)) { v = od; vi = oi; }
        }
        if (tid == 0) s_bi = vi;
    }
    __syncthreads();
    float picked = s_pd[s_bi];

    // top-50: warp-register bitonic top-k
    u64 k0, k1;
    {
        int i0 = wid * 64 + lane, i1 = i0 + 32;
        k0 = (i0 < 1000) ? ((((u64)__float_as_uint(s_pd[i0])) << 32) | (u32)(~i0)) : 0ull;
        k1 = (i1 < 1000) ? ((((u64)__float_as_uint(s_pd[i1])) << 32) | (u32)(~i1)) : 0ull;
    }
#pragma unroll
    for (int k = 2; k <= 64; k <<= 1) {
#pragma unroll
        for (int j = k >> 1; j > 0; j >>= 1) {
            if (j == 32) {
                u64 mxk = k0 > k1 ? k0 : k1;
                u64 mnk = k0 > k1 ? k1 : k0;
                k0 = mxk; k1 = mnk;
            } else {
                u64 o0 = __shfl_xor_sync(0xffffffffu, k0, j);
                u64 o1 = __shfl_xor_sync(0xffffffffu, k1, j);
                bool low = (lane & j) == 0;
                bool d0 = (lane & k) == 0;
                bool d1 = (((lane + 32) & k) == 0);
                bool t0 = (low == d0), t1 = (low == d1);
                k0 = t0 ? (k0 > o0 ? k0 : o0) : (k0 < o0 ? k0 : o0);
                k1 = t1 ? (k1 > o1 ? k1 : o1) : (k1 < o1 ? k1 : o1);
            }
        }
    }
    s_key[wid * 64 + lane] = k0;
    s_key[wid * 64 + 32 + lane] = k1;
    __syncthreads();
#pragma unroll
    for (int act = 8; act >= 1; act >>= 1) {
        if (wid < act) {
            u64 a0k = s_key[(2 * wid) * 64 + lane];
            u64 a1k = s_key[(2 * wid) * 64 + 32 + lane];
            u64 b0k = s_key[(2 * wid + 1) * 64 + 63 - lane];
            u64 b1k = s_key[(2 * wid + 1) * 64 + 31 - lane];
            k0 = a0k > b0k ? a0k : b0k;
            k1 = a1k > b1k ? a1k : b1k;
            { u64 mxk = k0 > k1 ? k0 : k1, mnk = k0 > k1 ? k1 : k0; k0 = mxk; k1 = mnk; }
#pragma unroll
            for (int j = 16; j > 0; j >>= 1) {
                u64 o0 = __shfl_xor_sync(0xffffffffu, k0, j);
                u64 o1 = __shfl_xor_sync(0xffffffffu, k1, j);
                bool tm = (lane & j) == 0;
                k0 = tm ? (k0 > o0 ? k0 : o0) : (k0 < o0 ? k0 : o0);
                k1 = tm ? (k1 > o1 ? k1 : o1) : (k1 < o1 ? k1 : o1);
            }
        }
        __syncthreads();
        if (act > 1 && wid < act) {
            s_key[wid * 64 + lane] = k0;
            s_key[wid * 64 + 32 + lane] = k1;
        }
        __syncthreads();
    }

    if (wid == 0) {
        float es = 0.f;
        u32 id = ~(u32)k0;
        float t0 = s_t[2 * id], t1 = s_t[2 * id + 1];
        out[2 + (b * 50 + lane) * 2]     = t0;
        out[2 + (b * 50 + lane) * 2 + 1] = t1;
        es = sl1(t0 - ex) + sl1(t1 - ey);
        if (lane < 18) {
            u32 id2 = ~(u32)k1;
            float u0 = s_t[2 * id2], u1 = s_t[2 * id2 + 1];
            int pos = 32 + lane;
            out[2 + (b * 50 + pos) * 2]     = u0;
            out[2 + (b * 50 + pos) * 2 + 1] = u1;
            es += sl1(u0 - ex) + sl1(u1 - ey);
        }
        es = wsum(es);
        if (lane == 0) {
            g_cls[b] = lse - picked;
            g_endsum[b] = es;
        }
    }
}

// ---------------- K4: final scalar reductions (warp-shuffle, 2 barriers) ----------------
__global__ void __launch_bounds__(512) reduce_kernel(float* __restrict__ out) {
    __shared__ float sw[48];
    int tid = threadIdx.x;
    int wid = tid >> 5, lane = tid & 31;

    float offs = 0.f;
    for (int i = tid; i < 2048; i += 512) offs += g_off_part[i];
    float cls = g_cls[tid];
    float ends = g_endsum[tid];

    offs = wsum(offs);
    cls  = wsum(cls);
    ends = wsum(ends);
    if (lane == 0) { sw[wid] = offs; sw[16 + wid] = cls; sw[32 + wid] = ends; }
    __syncthreads();
    if (tid < 32) {
        float vo = (lane < 16) ? sw[lane] : 0.f;
        float vc = (lane < 16) ? sw[16 + lane] : 0.f;
        float ve = (lane < 16) ? sw[32 + lane] : 0.f;
#pragma unroll
        for (int o = 8; o; o >>= 1) {
            vo += __shfl_xor_sync(0xffffffffu, vo, o);
            vc += __shfl_xor_sync(0xffffffffu, vc, o);
            ve += __shfl_xor_sync(0xffffffffu, ve, o);
        }
        if (lane == 0) {
            out[0] = vc / 512.0f;
            out[1] = vo / 1024000.0f + 3.0f * (ve / 51200.0f);
        }
    }
}

extern "C" void kernel_launch(void* const* d_in, const int* in_sizes, int n_in,
                              void* d_out, int out_size) {
    const float* osm   = (const float*)d_in[0];
    const float* at    = (const float*)d_in[1];
    const float* vf    = (const float*)d_in[2];
    const float* end   = (const float*)d_in[3];
    const float* ox_w1 = (const float*)d_in[5];
    const float* ox_b1 = (const float*)d_in[6];
    const float* ox_g1 = (const float*)d_in[7];
    const float* ox_be1= (const float*)d_in[8];
    const float* ox_w2 = (const float*)d_in[9];
    const float* ox_b2 = (const float*)d_in[10];
    const float* tp_w1 = (const float*)d_in[11];
    const float* tp_b1 = (const float*)d_in[12];
    const float* tp_g1 = (const float*)d_in[13];
    const float* tp_be1= (const float*)d_in[14];
    const float* tp_w2 = (const float*)d_in[15];
    const float* tp_b2 = (const float*)d_in[16];
    const float* tp_g2 = (const float*)d_in[17];
    const float* tp_be2= (const float*)d_in[18];
    const float* tp_w3 = (const float*)d_in[19];
    const float* tp_b3 = (const float*)d_in[20];
    float* out = (float*)d_out;

    setup_kernel<<<512, 1024>>>(osm, at, vf, ox_w1, ox_b1, tp_w1, tp_b1, tp_w2);
    dim3 g(4, 512);
    mlp_kernel<<<g, 256, MLP_DSMEM>>>(ox_w1, ox_g1, ox_be1, ox_w2, ox_b2,
                                      tp_w1, tp_g1, tp_be1, tp_w2, tp_b2,
                                      tp_g2, tp_be2, tp_w3, tp_b3, end);
    finalize_kernel<<<512, 512>>>(end, out);
    reduce_kernel<<<1, 512>>>(out);
}